// round 3
// baseline (speedup 1.0000x reference)
#include <cuda_runtime.h>
#include <cstdint>

#define TD 768     // input dim
#define TO 768     // output dim
#define TE 8       // experts
#define TH 7680    // hidden dim
#define TN 4096    // tokens

// ---- scratch (static device arrays; no allocations allowed) ----
__device__ int   g_counts[TE];
__device__ int   g_offsets[TE];
__device__ int   g_rank[TN];
__device__ int   g_eidx[TN];
__device__ float g_prob[TN];
__device__ int   g_perm[TN];                 // sorted position -> token id
__device__ float g_h[(size_t)TN * TH];       // hidden activations, permuted order (~126 MB)

// ---------------------------------------------------------------
__global__ void k_zero() {
    if (threadIdx.x < TE) g_counts[threadIdx.x] = 0;
}

// one warp per token: logits = x@Wg + bg, softmax over 8, keep top-1
__global__ void k_gate(const float* __restrict__ x, const float* __restrict__ Wg,
                       const float* __restrict__ bg) {
    int warp = (blockIdx.x * blockDim.x + threadIdx.x) >> 5;
    int lane = threadIdx.x & 31;
    if (warp >= TN) return;
    const float* xr = x + (size_t)warp * TD;
    float acc[TE];
#pragma unroll
    for (int e = 0; e < TE; e++) acc[e] = 0.f;
    for (int d = lane; d < TD; d += 32) {
        float xv = xr[d];
        const float* wr = Wg + (size_t)d * TE;
#pragma unroll
        for (int e = 0; e < TE; e++) acc[e] += xv * wr[e];
    }
#pragma unroll
    for (int e = 0; e < TE; e++) {
        float v = acc[e];
#pragma unroll
        for (int off = 16; off > 0; off >>= 1)
            v += __shfl_xor_sync(0xffffffffu, v, off);
        acc[e] = v;
    }
    if (lane == 0) {
        float mx = -1e30f;
        int am = 0;
#pragma unroll
        for (int e = 0; e < TE; e++) {
            float l = acc[e] + bg[e];
            acc[e] = l;
            if (l > mx) { mx = l; am = e; }
        }
        float s = 0.f;
#pragma unroll
        for (int e = 0; e < TE; e++) s += expf(acc[e] - mx);
        g_eidx[warp] = am;
        g_prob[warp] = 1.f / s;   // exp(mx - mx)/s
        g_rank[warp] = atomicAdd(&g_counts[am], 1);
    }
}

__global__ void k_scan() {
    int o = 0;
#pragma unroll
    for (int e = 0; e < TE; e++) { g_offsets[e] = o; o += g_counts[e]; }
}

__global__ void k_scatter() {
    int n = blockIdx.x * blockDim.x + threadIdx.x;
    if (n < TN) g_perm[g_offsets[g_eidx[n]] + g_rank[n]] = n;
}

// ---------------------------------------------------------------
// GEMM1: h[perm_pos, :] = relu( x[token, :] @ W1[e] + b1[e] )
// 128x128 tile, BK=16, 256 threads, 8x8 per thread, fp32.
__global__ void __launch_bounds__(256) k_gemm1(const float* __restrict__ x,
                                               const float* __restrict__ W1,
                                               const float* __restrict__ b1) {
    const int e   = blockIdx.z;
    const int cnt = g_counts[e];
    const int m0  = blockIdx.y * 128;
    if (m0 >= cnt) return;
    const int n0   = blockIdx.x * 128;
    const int base = g_offsets[e];
    const float* W = W1 + (size_t)e * TD * TH;

    __shared__ float As[16][128];
    __shared__ float Bs[16][128];

    const int tid = threadIdx.x;
    const int tx = tid & 15, ty = tid >> 4;

    // A gather: thread loads 8 consecutive k (2x float4) of one row.
    // Out-of-range rows clamp to a valid row; their results are discarded.
    const int amm  = tid >> 1;
    const int akq  = (tid & 1) * 8;
    const int arow = (m0 + amm < cnt) ? (m0 + amm) : (cnt - 1);
    const float* aptr = x + (size_t)g_perm[base + arow] * TD + akq;

    // B: thread loads 4 consecutive n of two k-rows (k and k+8)
    const int bkk = tid >> 5;
    const int bnn = (tid & 31) * 4;
    const float* bptr = W + (size_t)bkk * TH + n0 + bnn;

    float c[8][8];
#pragma unroll
    for (int i = 0; i < 8; i++)
#pragma unroll
        for (int j = 0; j < 8; j++) c[i][j] = 0.f;

    for (int k0 = 0; k0 < TD; k0 += 16) {
        float4 av0 = *(const float4*)(aptr + k0);
        float4 av1 = *(const float4*)(aptr + k0 + 4);
        float4 bv0 = *(const float4*)(bptr + (size_t)k0 * TH);
        float4 bv1 = *(const float4*)(bptr + (size_t)(k0 + 8) * TH);
        __syncthreads();
        As[akq + 0][amm] = av0.x; As[akq + 1][amm] = av0.y;
        As[akq + 2][amm] = av0.z; As[akq + 3][amm] = av0.w;
        As[akq + 4][amm] = av1.x; As[akq + 5][amm] = av1.y;
        As[akq + 6][amm] = av1.z; As[akq + 7][amm] = av1.w;
        *(float4*)&Bs[bkk][bnn]     = bv0;
        *(float4*)&Bs[bkk + 8][bnn] = bv1;
        __syncthreads();
#pragma unroll
        for (int kk = 0; kk < 16; kk++) {
            float a[8], b[8];
            *(float4*)&a[0] = *(const float4*)&As[kk][ty * 8];
            *(float4*)&a[4] = *(const float4*)&As[kk][ty * 8 + 4];
            *(float4*)&b[0] = *(const float4*)&Bs[kk][tx * 8];
            *(float4*)&b[4] = *(const float4*)&Bs[kk][tx * 8 + 4];
#pragma unroll
            for (int i = 0; i < 8; i++)
#pragma unroll
                for (int j = 0; j < 8; j++)
                    c[i][j] = fmaf(a[i], b[j], c[i][j]);
        }
    }

    float bb[8];
#pragma unroll
    for (int j = 0; j < 8; j++) bb[j] = b1[(size_t)e * TH + n0 + tx * 8 + j];
#pragma unroll
    for (int i = 0; i < 8; i++) {
        int r = m0 + ty * 8 + i;
        if (r < cnt) {
            float* hp = g_h + (size_t)(base + r) * TH + n0 + tx * 8;
            float4 v0, v1;
            v0.x = fmaxf(c[i][0] + bb[0], 0.f);
            v0.y = fmaxf(c[i][1] + bb[1], 0.f);
            v0.z = fmaxf(c[i][2] + bb[2], 0.f);
            v0.w = fmaxf(c[i][3] + bb[3], 0.f);
            v1.x = fmaxf(c[i][4] + bb[4], 0.f);
            v1.y = fmaxf(c[i][5] + bb[5], 0.f);
            v1.z = fmaxf(c[i][6] + bb[6], 0.f);
            v1.w = fmaxf(c[i][7] + bb[7], 0.f);
            *(float4*)hp       = v0;
            *(float4*)(hp + 4) = v1;
        }
    }
}

// GEMM2: out[token, :] = prob[token] * ( h[perm_pos, :] @ W2[e] + b2[e] )
__global__ void __launch_bounds__(256) k_gemm2(const float* __restrict__ W2,
                                               const float* __restrict__ b2,
                                               float* __restrict__ out) {
    const int e   = blockIdx.z;
    const int cnt = g_counts[e];
    const int m0  = blockIdx.y * 128;
    if (m0 >= cnt) return;
    const int n0   = blockIdx.x * 128;
    const int base = g_offsets[e];
    const float* W = W2 + (size_t)e * TH * TO;

    __shared__ float As[16][128];
    __shared__ float Bs[16][128];

    const int tid = threadIdx.x;
    const int tx = tid & 15, ty = tid >> 4;

    const int amm  = tid >> 1;
    const int akq  = (tid & 1) * 8;
    const int arow = (m0 + amm < cnt) ? (m0 + amm) : (cnt - 1);
    const float* aptr = g_h + (size_t)(base + arow) * TH + akq;

    const int bkk = tid >> 5;
    const int bnn = (tid & 31) * 4;
    const float* bptr = W + (size_t)bkk * TO + n0 + bnn;

    float c[8][8];
#pragma unroll
    for (int i = 0; i < 8; i++)
#pragma unroll
        for (int j = 0; j < 8; j++) c[i][j] = 0.f;

    for (int k0 = 0; k0 < TH; k0 += 16) {
        float4 av0 = *(const float4*)(aptr + k0);
        float4 av1 = *(const float4*)(aptr + k0 + 4);
        float4 bv0 = *(const float4*)(bptr + (size_t)k0 * TO);
        float4 bv1 = *(const float4*)(bptr + (size_t)(k0 + 8) * TO);
        __syncthreads();
        As[akq + 0][amm] = av0.x; As[akq + 1][amm] = av0.y;
        As[akq + 2][amm] = av0.z; As[akq + 3][amm] = av0.w;
        As[akq + 4][amm] = av1.x; As[akq + 5][amm] = av1.y;
        As[akq + 6][amm] = av1.z; As[akq + 7][amm] = av1.w;
        *(float4*)&Bs[bkk][bnn]     = bv0;
        *(float4*)&Bs[bkk + 8][bnn] = bv1;
        __syncthreads();
#pragma unroll
        for (int kk = 0; kk < 16; kk++) {
            float a[8], b[8];
            *(float4*)&a[0] = *(const float4*)&As[kk][ty * 8];
            *(float4*)&a[4] = *(const float4*)&As[kk][ty * 8 + 4];
            *(float4*)&b[0] = *(const float4*)&Bs[kk][tx * 8];
            *(float4*)&b[4] = *(const float4*)&Bs[kk][tx * 8 + 4];
#pragma unroll
            for (int i = 0; i < 8; i++)
#pragma unroll
                for (int j = 0; j < 8; j++)
                    c[i][j] = fmaf(a[i], b[j], c[i][j]);
        }
    }

    float bb[8];
#pragma unroll
    for (int j = 0; j < 8; j++) bb[j] = b2[(size_t)e * TO + n0 + tx * 8 + j];
#pragma unroll
    for (int i = 0; i < 8; i++) {
        int r = m0 + ty * 8 + i;
        if (r < cnt) {
            int token = g_perm[base + r];
            float p   = g_prob[token];
            float* op = out + (size_t)token * TO + n0 + tx * 8;
            float4 v0, v1;
            v0.x = p * (c[i][0] + bb[0]);
            v0.y = p * (c[i][1] + bb[1]);
            v0.z = p * (c[i][2] + bb[2]);
            v0.w = p * (c[i][3] + bb[3]);
            v1.x = p * (c[i][4] + bb[4]);
            v1.y = p * (c[i][5] + bb[5]);
            v1.z = p * (c[i][6] + bb[6]);
            v1.w = p * (c[i][7] + bb[7]);
            *(float4*)op       = v0;
            *(float4*)(op + 4) = v1;
        }
    }
}

// ---------------------------------------------------------------
extern "C" void kernel_launch(void* const* d_in, const int* in_sizes, int n_in,
                              void* d_out, int out_size) {
    (void)in_sizes; (void)n_in; (void)out_size;
    const float* x  = (const float*)d_in[0];
    const float* Wg = (const float*)d_in[1];
    const float* bg = (const float*)d_in[2];
    const float* W1 = (const float*)d_in[3];
    const float* b1 = (const float*)d_in[4];
    const float* W2 = (const float*)d_in[5];
    const float* b2 = (const float*)d_in[6];
    float* out = (float*)d_out;

    k_zero<<<1, 32>>>();
    k_gate<<<(TN * 32 + 255) / 256, 256>>>(x, Wg, bg);
    k_scan<<<1, 1>>>();
    k_scatter<<<(TN + 255) / 256, 256>>>();
    k_gemm1<<<dim3(TH / 128, TN / 128, TE), 256>>>(x, W1, b1);
    k_gemm2<<<dim3(TO / 128, TN / 128, TE), 256>>>(W2, b2, out);
}

// round 5
// speedup vs baseline: 2.0844x; 2.0844x over previous
#include <cuda_runtime.h>
#include <cuda_bf16.h>
#include <cstdint>

#define TD 768
#define TO 768
#define TE 8
#define TH 7680
#define TN 4096

#define BM 128
#define BN 128
#define BK 32          // fp32 K elements per stage
#define NTHREADS 256
#define SLD 40         // smem tile stride in bf16 elements (rows 80B apart)

// SMEM layout (bytes)
#define SM_BIAS  0
#define SM_PROB  512
#define SM_AHI   1024
#define TILE_B   (128 * SLD * 2)         // 10240
#define SM_ALO   (SM_AHI + TILE_B)
#define SM_BHI   (SM_AHI + 2 * TILE_B)
#define SM_BLO   (SM_AHI + 3 * TILE_B)
#define SM_STAGE 1024                    // epilogue staging reuses tile space
#define SM_TOTAL (1024 + 65536)          // 66560

// ---- scratch ----
__device__ int   g_counts[TE];
__device__ int   g_offsets[TE];
__device__ int   g_rank[TN];
__device__ int   g_eidx[TN];
__device__ float g_prob[TN];
__device__ int   g_perm[TN];
__device__ __nv_bfloat16 g_h_hi[(size_t)TN * TH];
__device__ __nv_bfloat16 g_h_lo[(size_t)TN * TH];

// ================= helpers =================
__device__ __forceinline__ uint32_t smem_to_u32(const void* p) {
    uint32_t a;
    asm("{ .reg .u64 t; cvta.to.shared.u64 t, %1; cvt.u32.u64 %0, t; }" : "=r"(a) : "l"(p));
    return a;
}
__device__ __forceinline__ void ldsm4(uint32_t* r, uint32_t addr) {
    asm volatile("ldmatrix.sync.aligned.m8n8.x4.shared.b16 {%0,%1,%2,%3}, [%4];"
                 : "=r"(r[0]), "=r"(r[1]), "=r"(r[2]), "=r"(r[3]) : "r"(addr));
}
__device__ __forceinline__ void mma16816(float* c, const uint32_t* a, const uint32_t* b) {
    asm volatile("mma.sync.aligned.m16n8k16.row.col.f32.bf16.bf16.f32 "
                 "{%0,%1,%2,%3}, {%4,%5,%6,%7}, {%8,%9}, {%0,%1,%2,%3};"
                 : "+f"(c[0]), "+f"(c[1]), "+f"(c[2]), "+f"(c[3])
                 : "r"(a[0]), "r"(a[1]), "r"(a[2]), "r"(a[3]), "r"(b[0]), "r"(b[1]));
}
__device__ __forceinline__ void split2(float a, float b, uint32_t& hi, uint32_t& lo) {
    __nv_bfloat16 ah = __float2bfloat16(a);
    __nv_bfloat16 bh = __float2bfloat16(b);
    __nv_bfloat16 al = __float2bfloat16(a - __bfloat162float(ah));
    __nv_bfloat16 bl = __float2bfloat16(b - __bfloat162float(bh));
    hi = (uint32_t)__bfloat16_as_ushort(ah) | ((uint32_t)__bfloat16_as_ushort(bh) << 16);
    lo = (uint32_t)__bfloat16_as_ushort(al) | ((uint32_t)__bfloat16_as_ushort(bl) << 16);
}

// ================= gating / routing =================
__global__ void k_zero() {
    if (threadIdx.x < TE) g_counts[threadIdx.x] = 0;
}

__global__ void k_gate(const float* __restrict__ x, const float* __restrict__ Wg,
                       const float* __restrict__ bg) {
    int warp = (blockIdx.x * blockDim.x + threadIdx.x) >> 5;
    int lane = threadIdx.x & 31;
    if (warp >= TN) return;
    const float* xr = x + (size_t)warp * TD;
    float acc[TE];
#pragma unroll
    for (int e = 0; e < TE; e++) acc[e] = 0.f;
    for (int d = lane; d < TD; d += 32) {
        float xv = xr[d];
        const float* wr = Wg + (size_t)d * TE;
#pragma unroll
        for (int e = 0; e < TE; e++) acc[e] += xv * wr[e];
    }
#pragma unroll
    for (int e = 0; e < TE; e++) {
        float v = acc[e];
#pragma unroll
        for (int off = 16; off > 0; off >>= 1) v += __shfl_xor_sync(0xffffffffu, v, off);
        acc[e] = v;
    }
    if (lane == 0) {
        float mx = -1e30f; int am = 0;
#pragma unroll
        for (int e = 0; e < TE; e++) {
            float l = acc[e] + bg[e];
            acc[e] = l;
            if (l > mx) { mx = l; am = e; }
        }
        float s = 0.f;
#pragma unroll
        for (int e = 0; e < TE; e++) s += expf(acc[e] - mx);
        g_eidx[warp] = am;
        g_prob[warp] = 1.f / s;
        g_rank[warp] = atomicAdd(&g_counts[am], 1);
    }
}

__global__ void k_scan() {
    int o = 0;
#pragma unroll
    for (int e = 0; e < TE; e++) { g_offsets[e] = o; o += g_counts[e]; }
}

__global__ void k_scatter() {
    int n = blockIdx.x * blockDim.x + threadIdx.x;
    if (n < TN) g_perm[g_offsets[g_eidx[n]] + g_rank[n]] = n;
}

// ================= shared mma compute phase =================
// warp tile: 64(m) x 32(n); 4 m16 x 4 n8 tiles; 3-pass hi/lo split
struct Frag { float c[4][4][4]; };

__device__ __forceinline__ void compute_stage(uint32_t sb, int wm, int wn, int lane,
                                              Frag& F) {
    const uint32_t aoff = ((uint32_t)((wm * 64 + (lane & 15)) * SLD + (lane >> 4) * 8)) * 2;
    const uint32_t boff = ((uint32_t)((wn * 32 + ((lane >> 4) & 1) * 8 + (lane & 7)) * SLD
                                      + ((lane >> 3) & 1) * 8)) * 2;
    const uint32_t aHi = sb + SM_AHI + aoff;
    const uint32_t aLo = sb + SM_ALO + aoff;
    const uint32_t bHi = sb + SM_BHI + boff;
    const uint32_t bLo = sb + SM_BLO + boff;
#pragma unroll
    for (int ks = 0; ks < 2; ks++) {
        const uint32_t kso = ks * 32;  // 16 elems * 2B
        uint32_t ah[4][4], bh[2][4];
#pragma unroll
        for (int mt = 0; mt < 4; mt++) ldsm4(ah[mt], aHi + mt * 16 * SLD * 2 + kso);
#pragma unroll
        for (int p = 0; p < 2; p++) ldsm4(bh[p], bHi + p * 16 * SLD * 2 + kso);
#pragma unroll
        for (int mt = 0; mt < 4; mt++)
#pragma unroll
            for (int nt = 0; nt < 4; nt++)
                mma16816(F.c[mt][nt], ah[mt], &bh[nt >> 1][(nt & 1) * 2]);
        uint32_t bl[2][4];
#pragma unroll
        for (int p = 0; p < 2; p++) ldsm4(bl[p], bLo + p * 16 * SLD * 2 + kso);
#pragma unroll
        for (int mt = 0; mt < 4; mt++)
#pragma unroll
            for (int nt = 0; nt < 4; nt++)
                mma16816(F.c[mt][nt], ah[mt], &bl[nt >> 1][(nt & 1) * 2]);
        uint32_t al[4][4];
#pragma unroll
        for (int mt = 0; mt < 4; mt++) ldsm4(al[mt], aLo + mt * 16 * SLD * 2 + kso);
#pragma unroll
        for (int mt = 0; mt < 4; mt++)
#pragma unroll
            for (int nt = 0; nt < 4; nt++)
                mma16816(F.c[mt][nt], al[mt], &bh[nt >> 1][(nt & 1) * 2]);
    }
}

// B tile fill: Bs[n][k] hi/lo from W[k][n] (row-major k). Coalesced (lane = n).
__device__ __forceinline__ void fill_B(char* smem, const float* __restrict__ W,
                                       int ldW, int n0, int k0, int wid, int lane) {
#pragma unroll
    for (int it = 0; it < 2; it++) {
        const int tsk = wid + it * 8;         // 0..15
        const int ng = tsk & 3, kg = tsk >> 2;
        const int n = ng * 32 + lane;
        const float* wp = W + (size_t)(k0 + kg * 8) * ldW + n0 + n;
        uint32_t hi[4], lo[4];
#pragma unroll
        for (int kk = 0; kk < 4; kk++) {
            float w0 = wp[(size_t)(2 * kk) * ldW];
            float w1 = wp[(size_t)(2 * kk + 1) * ldW];
            split2(w0, w1, hi[kk], lo[kk]);
        }
        const uint32_t o = ((uint32_t)(n * SLD + kg * 8)) * 2;
        *(uint4*)(smem + SM_BHI + o) = *(uint4*)hi;
        *(uint4*)(smem + SM_BLO + o) = *(uint4*)lo;
    }
}

// ================= GEMM1 =================
__global__ void __launch_bounds__(NTHREADS) k_gemm1(const float* __restrict__ x,
                                                    const float* __restrict__ W1,
                                                    const float* __restrict__ b1) {
    extern __shared__ char smem[];
    const int e   = blockIdx.z;
    const int cnt = g_counts[e];
    const int m0  = blockIdx.y * BM;
    if (m0 >= cnt) return;
    const int n0   = blockIdx.x * BN;
    const int base = g_offsets[e];
    const float* W = W1 + (size_t)e * TD * TH;

    const uint32_t sb = smem_to_u32(smem);
    const int tid = threadIdx.x, wid = tid >> 5, lane = tid & 31;
    const int wm = wid & 1, wn = wid >> 1;

    if (tid < 128) *(float*)(smem + SM_BIAS + tid * 4) = b1[(size_t)e * TH + n0 + tid];

    const int arow = tid >> 1;
    const int half = tid & 1;
    const int arowc = (m0 + arow < cnt) ? (m0 + arow) : (cnt - 1);
    const float* aptr = x + (size_t)g_perm[base + arowc] * TD + half * 16;

    Frag F;
#pragma unroll
    for (int mt = 0; mt < 4; mt++)
#pragma unroll
        for (int nt = 0; nt < 4; nt++)
#pragma unroll
            for (int i = 0; i < 4; i++) F.c[mt][nt][i] = 0.f;

    __syncthreads();
    for (int s = 0; s < TD / BK; s++) {
        const int k0 = s * BK;
        // A fill: 16 k per thread -> hi/lo bf16
#pragma unroll
        for (int q = 0; q < 4; q++) {
            float4 v = *(const float4*)(aptr + k0 + q * 4);
            uint32_t h0, l0, h1, l1;
            split2(v.x, v.y, h0, l0);
            split2(v.z, v.w, h1, l1);
            const uint32_t o = ((uint32_t)(arow * SLD + half * 16 + q * 4)) * 2;
            *(uint32_t*)(smem + SM_AHI + o) = h0;
            *(uint32_t*)(smem + SM_AHI + o + 4) = h1;
            *(uint32_t*)(smem + SM_ALO + o) = l0;
            *(uint32_t*)(smem + SM_ALO + o + 4) = l1;
        }
        fill_B(smem, W, TH, n0, k0, wid, lane);
        __syncthreads();
        compute_stage(sb, wm, wn, lane, F);
        __syncthreads();
    }

    // epilogue: relu(+bias) -> bf16 hi/lo staged (hi plane @SM_STAGE, lo @+32768)
#pragma unroll
    for (int mt = 0; mt < 4; mt++) {
        const int r0 = wm * 64 + mt * 16 + (lane >> 2);
        const int r1 = r0 + 8;
#pragma unroll
        for (int nt = 0; nt < 4; nt++) {
            const int cp = wn * 16 + nt * 4 + (lane & 3);   // uint32 col index (2 cols)
            float b0 = *(float*)(smem + SM_BIAS + (2 * cp) * 4);
            float b1v = *(float*)(smem + SM_BIAS + (2 * cp + 1) * 4);
            uint32_t h, l;
            split2(fmaxf(F.c[mt][nt][0] + b0, 0.f), fmaxf(F.c[mt][nt][1] + b1v, 0.f), h, l);
            *(uint32_t*)(smem + SM_STAGE + (r0 * 64 + cp) * 4) = h;
            *(uint32_t*)(smem + SM_STAGE + 32768 + (r0 * 64 + cp) * 4) = l;
            split2(fmaxf(F.c[mt][nt][2] + b0, 0.f), fmaxf(F.c[mt][nt][3] + b1v, 0.f), h, l);
            *(uint32_t*)(smem + SM_STAGE + (r1 * 64 + cp) * 4) = h;
            *(uint32_t*)(smem + SM_STAGE + 32768 + (r1 * 64 + cp) * 4) = l;
        }
    }
    __syncthreads();
    {
        const int r = tid >> 1, part = tid & 1;
        if (r < cnt - m0) {
            const size_t gro = (size_t)(base + m0 + r) * TH + n0;
            uint16_t* HP = (uint16_t*)g_h_hi;
            uint16_t* LP = (uint16_t*)g_h_lo;
#pragma unroll
            for (int j = 0; j < 8; j++) {
                uint4 qh = *(uint4*)(smem + SM_STAGE + (r * 64 + part * 32 + j * 4) * 4);
                uint4 ql = *(uint4*)(smem + SM_STAGE + 32768 + (r * 64 + part * 32 + j * 4) * 4);
                *(uint4*)(HP + gro + part * 64 + j * 8) = qh;
                *(uint4*)(LP + gro + part * 64 + j * 8) = ql;
            }
        }
    }
}

// ================= GEMM2 =================
__global__ void __launch_bounds__(NTHREADS) k_gemm2(const float* __restrict__ W2,
                                                    const float* __restrict__ b2,
                                                    float* __restrict__ out) {
    extern __shared__ char smem[];
    const int e   = blockIdx.z;
    const int cnt = g_counts[e];
    const int m0  = blockIdx.y * BM;
    if (m0 >= cnt) return;
    const int n0   = blockIdx.x * BN;
    const int base = g_offsets[e];
    const float* W = W2 + (size_t)e * TH * TO;

    const uint32_t sb = smem_to_u32(smem);
    const int tid = threadIdx.x, wid = tid >> 5, lane = tid & 31;
    const int wm = wid & 1, wn = wid >> 1;

    if (tid < 128) {
        *(float*)(smem + SM_BIAS + tid * 4) = b2[(size_t)e * TO + n0 + tid];
        const int rc = (m0 + tid < cnt) ? (m0 + tid) : (cnt - 1);
        *(float*)(smem + SM_PROB + tid * 4) = g_prob[g_perm[base + rc]];
    }

    const int arow = tid >> 1;
    const int half = tid & 1;
    const int arowc = (m0 + arow < cnt) ? (m0 + arow) : (cnt - 1);
    const uint16_t* hpi = (const uint16_t*)g_h_hi + (size_t)(base + arowc) * TH + half * 16;
    const uint16_t* lpi = (const uint16_t*)g_h_lo + (size_t)(base + arowc) * TH + half * 16;

    Frag F;
#pragma unroll
    for (int mt = 0; mt < 4; mt++)
#pragma unroll
        for (int nt = 0; nt < 4; nt++)
#pragma unroll
            for (int i = 0; i < 4; i++) F.c[mt][nt][i] = 0.f;

    __syncthreads();
    for (int s = 0; s < TH / BK; s++) {
        const int k0 = s * BK;
        // A fill: straight copy of bf16 hi/lo (16 k = one uint4 per plane)
        {
            uint4 qh0 = *(const uint4*)(hpi + k0);
            uint4 qh1 = *(const uint4*)(hpi + k0 + 8);
            uint4 ql0 = *(const uint4*)(lpi + k0);
            uint4 ql1 = *(const uint4*)(lpi + k0 + 8);
            const uint32_t o = ((uint32_t)(arow * SLD + half * 16)) * 2;
            *(uint4*)(smem + SM_AHI + o) = qh0;
            *(uint4*)(smem + SM_AHI + o + 16) = qh1;
            *(uint4*)(smem + SM_ALO + o) = ql0;
            *(uint4*)(smem + SM_ALO + o + 16) = ql1;
        }
        fill_B(smem, W, TO, n0, k0, wid, lane);
        __syncthreads();
        compute_stage(sb, wm, wn, lane, F);
        __syncthreads();
    }

    // epilogue: (c + bias) * prob -> fp32 stage -> scattered coalesced stores
#pragma unroll
    for (int mt = 0; mt < 4; mt++) {
        const int r0 = wm * 64 + mt * 16 + (lane >> 2);
        const int r1 = r0 + 8;
        const float p0 = *(float*)(smem + SM_PROB + r0 * 4);
        const float p1 = *(float*)(smem + SM_PROB + r1 * 4);
#pragma unroll
        for (int nt = 0; nt < 4; nt++) {
            const int col = wn * 32 + nt * 8 + (lane & 3) * 2;
            float b0 = *(float*)(smem + SM_BIAS + col * 4);
            float b1v = *(float*)(smem + SM_BIAS + (col + 1) * 4);
            *(float*)(smem + SM_STAGE + (r0 * 128 + col) * 4)     = p0 * (F.c[mt][nt][0] + b0);
            *(float*)(smem + SM_STAGE + (r0 * 128 + col + 1) * 4) = p0 * (F.c[mt][nt][1] + b1v);
            *(float*)(smem + SM_STAGE + (r1 * 128 + col) * 4)     = p1 * (F.c[mt][nt][2] + b0);
            *(float*)(smem + SM_STAGE + (r1 * 128 + col + 1) * 4) = p1 * (F.c[mt][nt][3] + b1v);
        }
    }
    __syncthreads();
    {
        const int r = tid >> 1, part = tid & 1;
        if (r < cnt - m0) {
            const int token = g_perm[base + m0 + r];
            float* op = out + (size_t)token * TO + n0 + part * 64;
#pragma unroll
            for (int j = 0; j < 16; j++) {
                float4 q = *(float4*)(smem + SM_STAGE + (r * 128 + part * 64 + j * 4) * 4);
                *(float4*)(op + j * 4) = q;
            }
        }
    }
}

// ---------------------------------------------------------------
extern "C" void kernel_launch(void* const* d_in, const int* in_sizes, int n_in,
                              void* d_out, int out_size) {
    (void)in_sizes; (void)n_in; (void)out_size;
    const float* x  = (const float*)d_in[0];
    const float* Wg = (const float*)d_in[1];
    const float* bg = (const float*)d_in[2];
    const float* W1 = (const float*)d_in[3];
    const float* b1 = (const float*)d_in[4];
    const float* W2 = (const float*)d_in[5];
    const float* b2 = (const float*)d_in[6];
    float* out = (float*)d_out;

    cudaFuncSetAttribute(k_gemm1, cudaFuncAttributeMaxDynamicSharedMemorySize, SM_TOTAL);
    cudaFuncSetAttribute(k_gemm2, cudaFuncAttributeMaxDynamicSharedMemorySize, SM_TOTAL);

    k_zero<<<1, 32>>>();
    k_gate<<<(TN * 32 + 255) / 256, 256>>>(x, Wg, bg);
    k_scan<<<1, 1>>>();
    k_scatter<<<(TN + 255) / 256, 256>>>();
    k_gemm1<<<dim3(TH / BN, TN / BM, TE), NTHREADS, SM_TOTAL>>>(x, W1, b1);
    k_gemm2<<<dim3(TO / BN, TN / BM, TE), NTHREADS, SM_TOTAL>>>(W2, b2, out);
}